// round 14
// baseline (speedup 1.0000x reference)
#include <cuda_runtime.h>
#include <cstdint>

#define E_NUM 60000
#define LDX   3712          // 29 * 128, row stride of x and out

// rna-rounded weights, TRANSPOSED [n][k] (static device globals: allowed)
__device__ float g_w0t[896 * 896];
__device__ float g_w1t[1536 * 1536];
__device__ float g_w2t[1280 * 1280];

__device__ __forceinline__ float to_tf32(float x) {
    uint32_t u;
    asm("cvt.rna.tf32.f32 %0, %1;" : "=r"(u) : "f"(x));
    return __uint_as_float(u);
}
__device__ __forceinline__ uint32_t s2u(const void* p) {
    uint32_t a;
    asm("{ .reg .u64 t; cvta.to.shared.u64 t, %1; cvt.u32.u64 %0, t; }" : "=r"(a) : "l"(p));
    return a;
}

// ---------------- weight prep (rna-rounded, transposed to [n][k]) ----------------

__global__ void prep_w0t_k(const float* __restrict__ src) {
    int i = blockIdx.x * blockDim.x + threadIdx.x;   // dst-linear: [n][k]
    if (i >= 896 * 896) return;
    int n = i / 896, k = i - n * 896;
    g_w0t[i] = to_tf32(src[k * 896 + n]);
}
// W'^T where W' = [[Wa, Wb], [-Wb, Wa]], src = [Wa | Wb] (H x 2H).
// dst[n*2H + k] = W'[k][n], rna-rounded.
__global__ void prep_so2t_k(const float* __restrict__ src, int H, int which) {
    float* dst = (which == 1) ? g_w1t : g_w2t;
    const int W2 = 2 * H;
    int i = blockIdx.x * blockDim.x + threadIdx.x;
    if (i >= W2 * W2) return;
    int n = i / W2, k = i - n * W2;
    float v;
    if (k < H) {
        v = src[k * W2 + n];
    } else {
        int kk = k - H;
        v = (n < H) ? -src[kk * W2 + n + H] : src[kk * W2 + n - H];
    }
    dst[i] = to_tf32(v);
}

// ---------------- GEMM: C = A(ExK, ld LDX) * W(KxN) (+bias), W given as Wt[N][K] ----
// Block tile 128x128x32, 128 threads (4 warps), warp grid 2x2, warp tile 64x64.
// 2 CTAs/SM. THREE smem stages: LDG for kt+2 issued at top of tile kt, STS at
// bottom -> load latency has a full tile to drain; per-tile sync guards nothing
// in flight. Fragments via ldmatrix.m8n8.x4 (conflict-free, stride 36).

#define AS_STRIDE 36
#define AS_BUF (128 * AS_STRIDE)    // 4608 floats / stage (A)
#define BS_BUF (128 * AS_STRIDE)    // 4608 floats / stage (Bt)
#define S_NUM 3
#define SMEM_BYTES (S_NUM * (AS_BUF + BS_BUF) * 4)   // 110592

__global__ __launch_bounds__(128, 2) void gemm_tf32_k(
    const float* __restrict__ A, const float* __restrict__ Bwt,
    const float* __restrict__ bias, float* __restrict__ C,
    int N, int K)
{
    extern __shared__ float smem[];
    float* As = smem;                      // [3][128 rows][36]  (row m, 32 k + pad)
    float* Bs = smem + S_NUM * AS_BUF;     // [3][128 rows][36]  (row n, 32 k + pad)

    const int tid  = threadIdx.x;
    const int lane = tid & 31;
    const int warp = tid >> 5;         // 0..3
    const int wm   = warp >> 1;        // 0..1  (64-row strip)
    const int wn   = warp & 1;         // 0..1  (64-col strip)
    const int bn   = blockIdx.x;       // fastest: A tile L2-reused across N strip
    const int bm   = blockIdx.y;

    const int lr = lane >> 2;          // 0..7
    const int lc = lane & 3;           // 0..3

    // ldmatrix lane-address offsets (floats), constant per thread.
    const int grp  = lane >> 3;        // 0..3
    const int row8 = lane & 7;
    const int aoff = (row8 + ((grp & 1) ? 8 : 0)) * AS_STRIDE + ((grp & 2) ? 4 : 0);
    const int boff = (row8 + ((grp & 2) ? 8 : 0)) * AS_STRIDE + ((grp & 1) ? 4 : 0);

    float acc[4][8][4];
#pragma unroll
    for (int a = 0; a < 4; a++)
#pragma unroll
        for (int b = 0; b < 8; b++)
#pragma unroll
            for (int c = 0; c < 4; c++) acc[a][b][c] = 0.f;

    const int ar   = tid >> 3;         // row base (0..15), rows ar + i*16
    const int asub = tid & 7;          // 16B sub-chunk

    const int ktiles = K >> 5;

    float4 aReg[8], bReg[4];

    auto ldgA = [&](int kt) {
#pragma unroll
        for (int i = 0; i < 8; i++) {
            int m = bm * 128 + ar + i * 16;
            if (m < E_NUM)
                aReg[i] = *reinterpret_cast<const float4*>(
                    A + (size_t)m * LDX + kt * 32 + asub * 4);
            else
                aReg[i] = make_float4(0.f, 0.f, 0.f, 0.f);
        }
    };
    // Bt tile: 128 n-rows x 32 k-floats = 1024 x16B chunks; halves of 4/thread.
    auto ldgB = [&](int kt, int h) {
#pragma unroll
        for (int i = 0; i < 4; i++) {
            int c = tid + (i + 4 * h) * 128;   // 0..1023
            int n = c >> 3, sub = c & 7;
            bReg[i] = *reinterpret_cast<const float4*>(
                Bwt + (size_t)(bn * 128 + n) * K + kt * 32 + sub * 4);
        }
    };
    auto stsA = [&](int slot) {
        float* a = As + slot * AS_BUF;
#pragma unroll
        for (int i = 0; i < 8; i++) {
            float4 v = aReg[i];
            v.x = to_tf32(v.x); v.y = to_tf32(v.y);
            v.z = to_tf32(v.z); v.w = to_tf32(v.w);
            *reinterpret_cast<float4*>(a + (ar + i * 16) * AS_STRIDE + asub * 4) = v;
        }
    };
    auto stsB = [&](int slot, int h) {
        float* b = Bs + slot * BS_BUF;
#pragma unroll
        for (int i = 0; i < 4; i++) {
            int c = tid + (i + 4 * h) * 128;
            int n = c >> 3, sub = c & 7;
            *reinterpret_cast<float4*>(b + n * AS_STRIDE + sub * 4) = bReg[i];
        }
    };

    auto compute_ks = [&](int slot, int ks) {
        const float* a  = As + slot * AS_BUF;
        const float* bt = Bs + slot * BS_BUF;
        const int k0 = ks * 8;
        uint32_t af[4][4], bf[8][2];
        const uint32_t a_u = s2u(a)  + (uint32_t)(aoff + k0) * 4u;
        const uint32_t b_u = s2u(bt) + (uint32_t)(boff + k0) * 4u;
#pragma unroll
        for (int im = 0; im < 4; im++) {
            uint32_t ad = a_u + (uint32_t)((wm * 64 + im * 16) * AS_STRIDE) * 4u;
            asm volatile(
                "ldmatrix.sync.aligned.m8n8.x4.shared.b16 {%0,%1,%2,%3}, [%4];"
                : "=r"(af[im][0]), "=r"(af[im][1]), "=r"(af[im][2]), "=r"(af[im][3])
                : "r"(ad));
        }
#pragma unroll
        for (int jp = 0; jp < 4; jp++) {
            uint32_t bd = b_u + (uint32_t)((wn * 64 + jp * 16) * AS_STRIDE) * 4u;
            asm volatile(
                "ldmatrix.sync.aligned.m8n8.x4.shared.b16 {%0,%1,%2,%3}, [%4];"
                : "=r"(bf[2 * jp][0]), "=r"(bf[2 * jp][1]),
                  "=r"(bf[2 * jp + 1][0]), "=r"(bf[2 * jp + 1][1])
                : "r"(bd));
        }
#pragma unroll
        for (int im = 0; im < 4; im++)
#pragma unroll
            for (int jn = 0; jn < 8; jn++) {
                asm volatile(
                    "mma.sync.aligned.m16n8k8.row.col.f32.tf32.tf32.f32 "
                    "{%0,%1,%2,%3}, {%4,%5,%6,%7}, {%8,%9}, {%0,%1,%2,%3};\n"
                    : "+f"(acc[im][jn][0]), "+f"(acc[im][jn][1]),
                      "+f"(acc[im][jn][2]), "+f"(acc[im][jn][3])
                    : "r"(af[im][0]), "r"(af[im][1]),
                      "r"(af[im][2]), "r"(af[im][3]),
                      "r"(bf[jn][0]), "r"(bf[jn][1]));
            }
    };

    // prologue: fill stages 0 and 1
    ldgA(0); ldgB(0, 0);
    stsA(0); stsB(0, 0);
    ldgB(0, 1); stsB(0, 1);
    if (ktiles > 1) {
        ldgA(1); ldgB(1, 0);
        stsA(1); stsB(1, 0);
        ldgB(1, 1); stsB(1, 1);
    }
    __syncthreads();

    int slot = 0;
    for (int kt = 0; kt < ktiles; kt++) {
        const bool pre = (kt + 2 < ktiles);
        const int s2 = (slot + 2 >= S_NUM) ? slot + 2 - S_NUM : slot + 2;
        if (pre) { ldgA(kt + 2); ldgB(kt + 2, 0); }
        compute_ks(slot, 0);
        compute_ks(slot, 1);
        if (pre) { stsB(s2, 0); ldgB(kt + 2, 1); }
        compute_ks(slot, 2);
        if (pre) { stsA(s2); stsB(s2, 1); }
        compute_ks(slot, 3);
        if (kt + 1 < ktiles) __syncthreads();
        slot++; if (slot == S_NUM) slot = 0;
    }

    // epilogue
#pragma unroll
    for (int im = 0; im < 4; im++) {
        int r0 = bm * 128 + wm * 64 + im * 16 + lr;
#pragma unroll
        for (int jn = 0; jn < 8; jn++) {
            int cg = bn * 128 + wn * 64 + jn * 8 + lc * 2;
            float bv0 = 0.f, bv1 = 0.f;
            if (bias) { bv0 = bias[cg]; bv1 = bias[cg + 1]; }
            if (r0 < E_NUM) {
                float2 v; v.x = acc[im][jn][0] + bv0; v.y = acc[im][jn][1] + bv1;
                *reinterpret_cast<float2*>(C + (size_t)r0 * LDX + cg) = v;
            }
            if (r0 + 8 < E_NUM) {
                float2 v; v.x = acc[im][jn][2] + bv0; v.y = acc[im][jn][3] + bv1;
                *reinterpret_cast<float2*>(C + (size_t)(r0 + 8) * LDX + cg) = v;
            }
        }
    }
}

// ---------------- launch ----------------

extern "C" void kernel_launch(void* const* d_in, const int* in_sizes, int n_in,
                              void* d_out, int out_size)
{
    const float* x  = (const float*)d_in[0];
    // d_in[1] = x_edge: unused by the reference
    const float* w0 = (const float*)d_in[2];
    const float* b0 = (const float*)d_in[3];
    const float* w1 = (const float*)d_in[4];
    const float* w2 = (const float*)d_in[5];
    float* out = (float*)d_out;

    prep_w0t_k<<<(896 * 896 + 255) / 256, 256>>>(w0);
    prep_so2t_k<<<(1536 * 1536 + 255) / 256, 256>>>(w1, 768, 1);
    prep_so2t_k<<<(1280 * 1280 + 255) / 256, 256>>>(w2, 640, 2);

    float *pw0, *pw1, *pw2;
    cudaGetSymbolAddress((void**)&pw0, g_w0t);
    cudaGetSymbolAddress((void**)&pw1, g_w1t);
    cudaGetSymbolAddress((void**)&pw2, g_w2t);

    cudaFuncSetAttribute(gemm_tf32_k,
                         cudaFuncAttributeMaxDynamicSharedMemorySize, SMEM_BYTES);

    const int mb = (E_NUM + 127) / 128;   // 469
    // m=0: (E,896) @ (896,896) + bias  -> out cols 0..895
    gemm_tf32_k<<<dim3(7, mb), 128, SMEM_BYTES>>>(x,        pw0, b0,      out,        896,  896);
    // m=1: (E,1536) @ (1536,1536)      -> out cols 896..2431
    gemm_tf32_k<<<dim3(12, mb), 128, SMEM_BYTES>>>(x + 896,  pw1, nullptr, out + 896,  1536, 1536);
    // m=2: (E,1280) @ (1280,1280)      -> out cols 2432..3711
    gemm_tf32_k<<<dim3(10, mb), 128, SMEM_BYTES>>>(x + 2432, pw2, nullptr, out + 2432, 1280, 1280);
}

// round 15
// speedup vs baseline: 1.1584x; 1.1584x over previous
#include <cuda_runtime.h>
#include <cstdint>

#define E_NUM 60000
#define LDX   3712          // 29 * 128, row stride of x and out

// rna-rounded weights in mma-fragment order (static device globals: allowed)
// layout: [kt][jb][g][lane][4]  (jb = n/8, g = kstep-pair 0..1)
//   float4 = (b0@ks_even, b1@ks_even, b0@ks_odd, b1@ks_odd)
//   b0 = W'[kt*32 + ks*8 +     (lane&3)][jb*8 + (lane>>2)]
//   b1 = W'[kt*32 + ks*8 + 4 + (lane&3)][jb*8 + (lane>>2)]
__device__ float g_w0f[896 * 896];
__device__ float g_w1f[1536 * 1536];
__device__ float g_w2f[1280 * 1280];

__device__ __forceinline__ float to_tf32(float x) {
    uint32_t u;
    asm("cvt.rna.tf32.f32 %0, %1;" : "=r"(u) : "f"(x));
    return __uint_as_float(u);
}
__device__ __forceinline__ uint32_t s2u(const void* p) {
    uint32_t a;
    asm("{ .reg .u64 t; cvta.to.shared.u64 t, %1; cvt.u32.u64 %0, t; }" : "=r"(a) : "l"(p));
    return a;
}

// ---------------- weight prep: fragment-order, rna-rounded ----------------
// i = (((kt*NB + jb)*2 + g)*32 + lane)*4 + q
//   k = kt*32 + (g*2 + (q>>1))*8 + (q&1)*4 + (lane&3)
//   n = jb*8 + (lane>>2)

__global__ void prep_w0f_k(const float* __restrict__ src) {
    int i = blockIdx.x * blockDim.x + threadIdx.x;
    if (i >= 896 * 896) return;
    const int NB = 896 / 8;
    int q = i & 3, lane = (i >> 2) & 31, g = (i >> 7) & 1;
    int rest = i >> 8;
    int jb = rest % NB, kt = rest / NB;
    int k = kt * 32 + (g * 2 + (q >> 1)) * 8 + (q & 1) * 4 + (lane & 3);
    int n = jb * 8 + (lane >> 2);
    g_w0f[i] = to_tf32(src[k * 896 + n]);
}
// W' = [[Wa, Wb], [-Wb, Wa]] from src = [Wa | Wb] (H x 2H)
__global__ void prep_so2f_k(const float* __restrict__ src, int H, int which) {
    float* dst = (which == 1) ? g_w1f : g_w2f;
    const int W2 = 2 * H;
    const int NB = W2 / 8;
    int i = blockIdx.x * blockDim.x + threadIdx.x;
    if (i >= W2 * W2) return;
    int q = i & 3, lane = (i >> 2) & 31, g = (i >> 7) & 1;
    int rest = i >> 8;
    int jb = rest % NB, kt = rest / NB;
    int k = kt * 32 + (g * 2 + (q >> 1)) * 8 + (q & 1) * 4 + (lane & 3);
    int n = jb * 8 + (lane >> 2);
    float v;
    if (k < H) {
        v = src[k * W2 + n];
    } else {
        int kk = k - H;
        v = (n < H) ? -src[kk * W2 + n + H] : src[kk * W2 + n - H];
    }
    dst[i] = to_tf32(v);
}

// ---------------- GEMM: C = A(ExK, ld LDX) * W(KxN) (+bias) ----------------
// Block tile 128x128x32, 128 threads (4 warps), warp grid 2x2, warp tile 64x64.
// 2 CTAs/SM. A: LDG->rna->STS.128, double-buffered smem, ldmatrix fragments.
// B: fragment-order gmem -> registers via coalesced LDG.128 (no smem at all);
// wm-pair warps read identical lines (L1 dedup). Prefetch 2 ksteps ahead.

#define AS_STRIDE 36
#define AS_BUF (128 * AS_STRIDE)    // 4608 floats / stage
#define SMEM_BYTES (2 * AS_BUF * 4) // 36864

__global__ __launch_bounds__(128, 2) void gemm_tf32_k(
    const float* __restrict__ A, const float* __restrict__ Bf,
    const float* __restrict__ bias, float* __restrict__ C,
    int N, int K)
{
    extern __shared__ float smem[];
    float* As = smem;                  // [2][128 rows][36]

    const int tid  = threadIdx.x;
    const int lane = tid & 31;
    const int warp = tid >> 5;         // 0..3
    const int wm   = warp >> 1;        // 0..1  (64-row strip)
    const int wn   = warp & 1;         // 0..1  (64-col strip)
    const int bn   = blockIdx.x;
    const int bm   = blockIdx.y;

    const int lr = lane >> 2;          // 0..7
    const int lc = lane & 3;           // 0..3

    // ldmatrix A lane-address offset (floats), constant per thread.
    const int grp  = lane >> 3;
    const int row8 = lane & 7;
    const int aoff = (row8 + ((grp & 1) ? 8 : 0)) * AS_STRIDE + ((grp & 2) ? 4 : 0);

    const int NB = N >> 3;
    const int jbase = bn * 16 + wn * 8;          // global jb base for this warp
    const float4* __restrict__ Bp = reinterpret_cast<const float4*>(Bf);

    float acc[4][8][4];
#pragma unroll
    for (int a = 0; a < 4; a++)
#pragma unroll
        for (int b = 0; b < 8; b++)
#pragma unroll
            for (int c = 0; c < 4; c++) acc[a][b][c] = 0.f;

    const int ar   = tid >> 3;         // A row base (0..15), rows ar + i*16
    const int asub = tid & 7;          // 16B sub-chunk

    const int ktiles = K >> 5;

    float4 aReg[8];
    float4 B0[8], B1[8];               // kstep-pair fragment buffers

    auto ldgA = [&](int kt) {
#pragma unroll
        for (int i = 0; i < 8; i++) {
            int m = bm * 128 + ar + i * 16;
            if (m < E_NUM)
                aReg[i] = *reinterpret_cast<const float4*>(
                    A + (size_t)m * LDX + kt * 32 + asub * 4);
            else
                aReg[i] = make_float4(0.f, 0.f, 0.f, 0.f);
        }
    };
    auto stsA = [&](int buf) {
        float* a = As + buf * AS_BUF;
#pragma unroll
        for (int i = 0; i < 8; i++) {
            float4 v = aReg[i];
            v.x = to_tf32(v.x); v.y = to_tf32(v.y);
            v.z = to_tf32(v.z); v.w = to_tf32(v.w);
            *reinterpret_cast<float4*>(a + (ar + i * 16) * AS_STRIDE + asub * 4) = v;
        }
    };
    auto ldgB = [&](int kt, int g, float4* dst) {
#pragma unroll
        for (int jn = 0; jn < 8; jn++)
            dst[jn] = Bp[((size_t)kt * NB + jbase + jn) * 64 + g * 32 + lane];
    };

    // one kstep: ks in 0..3; uses pair buffer B (g = ks>>1), half = ks&1
    auto compute_ks = [&](int buf, int ks, const float4* Bv) {
        const float* a = As + buf * AS_BUF;
        const int k0 = ks * 8;
        const int hi = ks & 1;
        uint32_t af[4][4];
        const uint32_t a_u = s2u(a) + (uint32_t)(aoff + k0) * 4u;
#pragma unroll
        for (int im = 0; im < 4; im++) {
            uint32_t ad = a_u + (uint32_t)((wm * 64 + im * 16) * AS_STRIDE) * 4u;
            asm volatile(
                "ldmatrix.sync.aligned.m8n8.x4.shared.b16 {%0,%1,%2,%3}, [%4];"
                : "=r"(af[im][0]), "=r"(af[im][1]), "=r"(af[im][2]), "=r"(af[im][3])
                : "r"(ad));
        }
#pragma unroll
        for (int im = 0; im < 4; im++)
#pragma unroll
            for (int jn = 0; jn < 8; jn++) {
                uint32_t b0 = __float_as_uint(hi ? Bv[jn].z : Bv[jn].x);
                uint32_t b1 = __float_as_uint(hi ? Bv[jn].w : Bv[jn].y);
                asm volatile(
                    "mma.sync.aligned.m16n8k8.row.col.f32.tf32.tf32.f32 "
                    "{%0,%1,%2,%3}, {%4,%5,%6,%7}, {%8,%9}, {%0,%1,%2,%3};\n"
                    : "+f"(acc[im][jn][0]), "+f"(acc[im][jn][1]),
                      "+f"(acc[im][jn][2]), "+f"(acc[im][jn][3])
                    : "r"(af[im][0]), "r"(af[im][1]),
                      "r"(af[im][2]), "r"(af[im][3]),
                      "r"(b0), "r"(b1));
            }
    };

    // prologue
    ldgA(0); stsA(0);
    ldgB(0, 0, B0);
    ldgB(0, 1, B1);
    __syncthreads();

    int buf = 0;
    for (int kt = 0; kt < ktiles; kt++) {
        const bool nxt = (kt + 1 < ktiles);
        if (nxt) ldgA(kt + 1);
        compute_ks(buf, 0, B0);
        compute_ks(buf, 1, B0);
        if (nxt) ldgB(kt + 1, 0, B0);        // B0 dead; prefetch next tile
        compute_ks(buf, 2, B1);
        compute_ks(buf, 3, B1);
        if (nxt) {
            ldgB(kt + 1, 1, B1);             // B1 dead; prefetch next tile
            stsA(buf ^ 1);
            __syncthreads();
        }
        buf ^= 1;
    }

    // epilogue
#pragma unroll
    for (int im = 0; im < 4; im++) {
        int r0 = bm * 128 + wm * 64 + im * 16 + lr;
#pragma unroll
        for (int jn = 0; jn < 8; jn++) {
            int cg = bn * 128 + wn * 64 + jn * 8 + lc * 2;
            float bv0 = 0.f, bv1 = 0.f;
            if (bias) { bv0 = bias[cg]; bv1 = bias[cg + 1]; }
            if (r0 < E_NUM) {
                float2 v; v.x = acc[im][jn][0] + bv0; v.y = acc[im][jn][1] + bv1;
                *reinterpret_cast<float2*>(C + (size_t)r0 * LDX + cg) = v;
            }
            if (r0 + 8 < E_NUM) {
                float2 v; v.x = acc[im][jn][2] + bv0; v.y = acc[im][jn][3] + bv1;
                *reinterpret_cast<float2*>(C + (size_t)(r0 + 8) * LDX + cg) = v;
            }
        }
    }
}

// ---------------- launch ----------------

extern "C" void kernel_launch(void* const* d_in, const int* in_sizes, int n_in,
                              void* d_out, int out_size)
{
    const float* x  = (const float*)d_in[0];
    // d_in[1] = x_edge: unused by the reference
    const float* w0 = (const float*)d_in[2];
    const float* b0 = (const float*)d_in[3];
    const float* w1 = (const float*)d_in[4];
    const float* w2 = (const float*)d_in[5];
    float* out = (float*)d_out;

    prep_w0f_k<<<(896 * 896 + 255) / 256, 256>>>(w0);
    prep_so2f_k<<<(1536 * 1536 + 255) / 256, 256>>>(w1, 768, 1);
    prep_so2f_k<<<(1280 * 1280 + 255) / 256, 256>>>(w2, 640, 2);

    float *pw0, *pw1, *pw2;
    cudaGetSymbolAddress((void**)&pw0, g_w0f);
    cudaGetSymbolAddress((void**)&pw1, g_w1f);
    cudaGetSymbolAddress((void**)&pw2, g_w2f);

    cudaFuncSetAttribute(gemm_tf32_k,
                         cudaFuncAttributeMaxDynamicSharedMemorySize, SMEM_BYTES);

    const int mb = (E_NUM + 127) / 128;   // 469
    // m=0: (E,896) @ (896,896) + bias  -> out cols 0..895
    gemm_tf32_k<<<dim3(7, mb), 128, SMEM_BYTES>>>(x,        pw0, b0,      out,        896,  896);
    // m=1: (E,1536) @ (1536,1536)      -> out cols 896..2431
    gemm_tf32_k<<<dim3(12, mb), 128, SMEM_BYTES>>>(x + 896,  pw1, nullptr, out + 896,  1536, 1536);
    // m=2: (E,1280) @ (1280,1280)      -> out cols 2432..3711
    gemm_tf32_k<<<dim3(10, mb), 128, SMEM_BYTES>>>(x + 2432, pw2, nullptr, out + 2432, 1280, 1280);
}

// round 16
// speedup vs baseline: 1.1948x; 1.0314x over previous
#include <cuda_runtime.h>
#include <cstdint>

#define E_NUM 60000
#define LDX   3712          // 29 * 128, row stride of x and out

// rna-rounded weights in mma-fragment order (static device globals: allowed)
// layout: [kt][jb][g][lane][4]  (jb = n/8, g = kstep-pair 0..1)
__device__ float g_w0f[896 * 896];
__device__ float g_w1f[1536 * 1536];
__device__ float g_w2f[1280 * 1280];

__device__ __forceinline__ float to_tf32(float x) {
    uint32_t u;
    asm("cvt.rna.tf32.f32 %0, %1;" : "=r"(u) : "f"(x));
    return __uint_as_float(u);
}
__device__ __forceinline__ uint32_t s2u(const void* p) {
    uint32_t a;
    asm("{ .reg .u64 t; cvta.to.shared.u64 t, %1; cvt.u32.u64 %0, t; }" : "=r"(a) : "l"(p));
    return a;
}

// ---------------- weight prep: fragment-order, rna-rounded ----------------

__global__ void prep_w0f_k(const float* __restrict__ src) {
    int i = blockIdx.x * blockDim.x + threadIdx.x;
    if (i >= 896 * 896) return;
    const int NB = 896 / 8;
    int q = i & 3, lane = (i >> 2) & 31, g = (i >> 7) & 1;
    int rest = i >> 8;
    int jb = rest % NB, kt = rest / NB;
    int k = kt * 32 + (g * 2 + (q >> 1)) * 8 + (q & 1) * 4 + (lane & 3);
    int n = jb * 8 + (lane >> 2);
    g_w0f[i] = to_tf32(src[k * 896 + n]);
}
// W' = [[Wa, Wb], [-Wb, Wa]] from src = [Wa | Wb] (H x 2H)
__global__ void prep_so2f_k(const float* __restrict__ src, int H, int which) {
    float* dst = (which == 1) ? g_w1f : g_w2f;
    const int W2 = 2 * H;
    const int NB = W2 / 8;
    int i = blockIdx.x * blockDim.x + threadIdx.x;
    if (i >= W2 * W2) return;
    int q = i & 3, lane = (i >> 2) & 31, g = (i >> 7) & 1;
    int rest = i >> 8;
    int jb = rest % NB, kt = rest / NB;
    int k = kt * 32 + (g * 2 + (q >> 1)) * 8 + (q & 1) * 4 + (lane & 3);
    int n = jb * 8 + (lane >> 2);
    float v;
    if (k < H) {
        v = src[k * W2 + n];
    } else {
        int kk = k - H;
        v = (n < H) ? -src[kk * W2 + n + H] : src[kk * W2 + n - H];
    }
    dst[i] = to_tf32(v);
}

// ---------------- GEMM: C = A(ExK, ld LDX) * W(KxN) (+bias) ----------------
// Block tile 128x128x32, 128 threads (4 warps), warp grid 2x2, warp tile 64x64.
// 2 CTAs/SM. A smem is PAIR-PRIVATE: wm-pair (warps 2wm,2wm+1) loads/stores
// only rows wm*64..wm*64+63 and syncs with bar.sync(wm+1, 64) — no block-wide
// barrier anywhere; pairs drift independently. B: fragment-order gmem ->
// registers (LDG.128, no smem). Fragments via ldmatrix.m8n8.x4.

#define AS_STRIDE 36
#define AS_BUF (128 * AS_STRIDE)    // 4608 floats / stage
#define SMEM_BYTES (2 * AS_BUF * 4) // 36864

__global__ __launch_bounds__(128, 2) void gemm_tf32_k(
    const float* __restrict__ A, const float* __restrict__ Bf,
    const float* __restrict__ bias, float* __restrict__ C,
    int N, int K)
{
    extern __shared__ float smem[];
    float* As = smem;                  // [2][128 rows][36]

    const int tid  = threadIdx.x;
    const int lane = tid & 31;
    const int warp = tid >> 5;         // 0..3
    const int wm   = warp >> 1;        // 0..1  (64-row strip; pair id)
    const int wn   = warp & 1;         // 0..1  (64-col strip)
    const int bn   = blockIdx.x;
    const int bm   = blockIdx.y;

    const int lr = lane >> 2;          // 0..7
    const int lc = lane & 3;           // 0..3

    // ldmatrix A lane-address offset (floats), constant per thread.
    const int grp  = lane >> 3;
    const int row8 = lane & 7;
    const int aoff = (row8 + ((grp & 1) ? 8 : 0)) * AS_STRIDE + ((grp & 2) ? 4 : 0);

    const int NB = N >> 3;
    const int jbase = bn * 16 + wn * 8;          // global jb base for this warp
    const float4* __restrict__ Bp = reinterpret_cast<const float4*>(Bf);

    float acc[4][8][4];
#pragma unroll
    for (int a = 0; a < 4; a++)
#pragma unroll
        for (int b = 0; b < 8; b++)
#pragma unroll
            for (int c = 0; c < 4; c++) acc[a][b][c] = 0.f;

    // pair-private A loading: 64 threads cover 64 rows x 32 floats
    const int tp   = tid & 63;         // thread-in-pair
    const int arow = wm * 64 + (tp >> 3);   // + i*8, i=0..7
    const int asub = tp & 7;           // 16B sub-chunk

    const int ktiles = K >> 5;

    float4 aReg[8];
    float4 B0[8], B1[8];               // kstep-pair fragment buffers

    auto barrier_pair = [&]() {
        asm volatile("bar.sync %0, 64;" :: "r"(wm + 1) : "memory");
    };

    auto ldgA = [&](int kt) {
#pragma unroll
        for (int i = 0; i < 8; i++) {
            int m = bm * 128 + arow + i * 8;
            if (m < E_NUM)
                aReg[i] = *reinterpret_cast<const float4*>(
                    A + (size_t)m * LDX + kt * 32 + asub * 4);
            else
                aReg[i] = make_float4(0.f, 0.f, 0.f, 0.f);
        }
    };
    auto stsA = [&](int buf) {
        float* a = As + buf * AS_BUF;
#pragma unroll
        for (int i = 0; i < 8; i++) {
            float4 v = aReg[i];
            v.x = to_tf32(v.x); v.y = to_tf32(v.y);
            v.z = to_tf32(v.z); v.w = to_tf32(v.w);
            *reinterpret_cast<float4*>(a + (arow + i * 8) * AS_STRIDE + asub * 4) = v;
        }
    };
    auto ldgB = [&](int kt, int g, float4* dst) {
#pragma unroll
        for (int jn = 0; jn < 8; jn++)
            dst[jn] = Bp[((size_t)kt * NB + jbase + jn) * 64 + g * 32 + lane];
    };

    // one kstep: ks in 0..3; uses pair buffer Bv (g = ks>>1), half = ks&1
    auto compute_ks = [&](int buf, int ks, const float4* Bv) {
        const float* a = As + buf * AS_BUF;
        const int k0 = ks * 8;
        const int hi = ks & 1;
        uint32_t af[4][4];
        const uint32_t a_u = s2u(a) + (uint32_t)(aoff + k0) * 4u;
#pragma unroll
        for (int im = 0; im < 4; im++) {
            uint32_t ad = a_u + (uint32_t)((wm * 64 + im * 16) * AS_STRIDE) * 4u;
            asm volatile(
                "ldmatrix.sync.aligned.m8n8.x4.shared.b16 {%0,%1,%2,%3}, [%4];"
                : "=r"(af[im][0]), "=r"(af[im][1]), "=r"(af[im][2]), "=r"(af[im][3])
                : "r"(ad));
        }
#pragma unroll
        for (int im = 0; im < 4; im++)
#pragma unroll
            for (int jn = 0; jn < 8; jn++) {
                uint32_t b0 = __float_as_uint(hi ? Bv[jn].z : Bv[jn].x);
                uint32_t b1 = __float_as_uint(hi ? Bv[jn].w : Bv[jn].y);
                asm volatile(
                    "mma.sync.aligned.m16n8k8.row.col.f32.tf32.tf32.f32 "
                    "{%0,%1,%2,%3}, {%4,%5,%6,%7}, {%8,%9}, {%0,%1,%2,%3};\n"
                    : "+f"(acc[im][jn][0]), "+f"(acc[im][jn][1]),
                      "+f"(acc[im][jn][2]), "+f"(acc[im][jn][3])
                    : "r"(af[im][0]), "r"(af[im][1]),
                      "r"(af[im][2]), "r"(af[im][3]),
                      "r"(b0), "r"(b1));
            }
    };

    // prologue
    ldgA(0); stsA(0);
    ldgB(0, 0, B0);
    ldgB(0, 1, B1);
    barrier_pair();

    int buf = 0;
    for (int kt = 0; kt < ktiles; kt++) {
        const bool nxt = (kt + 1 < ktiles);
        if (nxt) ldgA(kt + 1);
        compute_ks(buf, 0, B0);
        compute_ks(buf, 1, B0);
        if (nxt) ldgB(kt + 1, 0, B0);        // B0 dead; prefetch next tile
        compute_ks(buf, 2, B1);
        compute_ks(buf, 3, B1);
        if (nxt) {
            ldgB(kt + 1, 1, B1);             // B1 dead; prefetch next tile
            stsA(buf ^ 1);
            barrier_pair();                  // pair-local: both warps wrote/read
        }
        buf ^= 1;
    }

    // epilogue (register-only; no sync needed)
#pragma unroll
    for (int im = 0; im < 4; im++) {
        int r0 = bm * 128 + wm * 64 + im * 16 + lr;
#pragma unroll
        for (int jn = 0; jn < 8; jn++) {
            int cg = bn * 128 + wn * 64 + jn * 8 + lc * 2;
            float bv0 = 0.f, bv1 = 0.f;
            if (bias) { bv0 = bias[cg]; bv1 = bias[cg + 1]; }
            if (r0 < E_NUM) {
                float2 v; v.x = acc[im][jn][0] + bv0; v.y = acc[im][jn][1] + bv1;
                *reinterpret_cast<float2*>(C + (size_t)r0 * LDX + cg) = v;
            }
            if (r0 + 8 < E_NUM) {
                float2 v; v.x = acc[im][jn][2] + bv0; v.y = acc[im][jn][3] + bv1;
                *reinterpret_cast<float2*>(C + (size_t)(r0 + 8) * LDX + cg) = v;
            }
        }
    }
}

// ---------------- launch ----------------

extern "C" void kernel_launch(void* const* d_in, const int* in_sizes, int n_in,
                              void* d_out, int out_size)
{
    const float* x  = (const float*)d_in[0];
    // d_in[1] = x_edge: unused by the reference
    const float* w0 = (const float*)d_in[2];
    const float* b0 = (const float*)d_in[3];
    const float* w1 = (const float*)d_in[4];
    const float* w2 = (const float*)d_in[5];
    float* out = (float*)d_out;

    prep_w0f_k<<<(896 * 896 + 255) / 256, 256>>>(w0);
    prep_so2f_k<<<(1536 * 1536 + 255) / 256, 256>>>(w1, 768, 1);
    prep_so2f_k<<<(1280 * 1280 + 255) / 256, 256>>>(w2, 640, 2);

    float *pw0, *pw1, *pw2;
    cudaGetSymbolAddress((void**)&pw0, g_w0f);
    cudaGetSymbolAddress((void**)&pw1, g_w1f);
    cudaGetSymbolAddress((void**)&pw2, g_w2f);

    cudaFuncSetAttribute(gemm_tf32_k,
                         cudaFuncAttributeMaxDynamicSharedMemorySize, SMEM_BYTES);

    const int mb = (E_NUM + 127) / 128;   // 469
    // m=0: (E,896) @ (896,896) + bias  -> out cols 0..895
    gemm_tf32_k<<<dim3(7, mb), 128, SMEM_BYTES>>>(x,        pw0, b0,      out,        896,  896);
    // m=1: (E,1536) @ (1536,1536)      -> out cols 896..2431
    gemm_tf32_k<<<dim3(12, mb), 128, SMEM_BYTES>>>(x + 896,  pw1, nullptr, out + 896,  1536, 1536);
    // m=2: (E,1280) @ (1280,1280)      -> out cols 2432..3711
    gemm_tf32_k<<<dim3(10, mb), 128, SMEM_BYTES>>>(x + 2432, pw2, nullptr, out + 2432, 1280, 1280);
}